// round 4
// baseline (speedup 1.0000x reference)
#include <cuda_runtime.h>
#include <cuda_bf16.h>
#include <math.h>

// BFP quant-dequant: [8192, 12284] fp32, BLOCK_SIZE=8 along last dim, 8-bit
// shared exponent + 8-bit signed mantissa (qmin=-128, qmax=127).
// step = 2^(frexp_exp(maxabs) - 7); out = clip(rint(x/step), -128, 127) * step.
//
// One thread handles one 8-float block: two float4 loads + two float4 stores.
// A warp covers 1024 contiguous bytes -> fully coalesced LDG.128/STG.128.
// 12284 % 8 == 4: the last block of each row has 4 real elements; the padded
// half contributes zeros to the max (no effect) and is never written.
// Row length 12284 * 4 B is 16B-aligned, so float4 access is legal everywhere.

#define ROWS    8192
#define COLS    12284
#define NBLK    1536   // ceil(12284 / 8)
#define FULLBLK 1535   // last block has only 4 real elements

__global__ __launch_bounds__(256, 8)
void bfp_qdq_kernel(const float* __restrict__ x, float* __restrict__ out)
{
    const int t = blockIdx.x * 256 + threadIdx.x;          // block-of-8 index in row
    const long long rowoff = (long long)blockIdx.y * COLS;
    const float4* __restrict__ src = reinterpret_cast<const float4*>(x + rowoff);
    float4*       __restrict__ dst = reinterpret_cast<float4*>(out + rowoff);

    const bool full = (t < FULLBLK);

    float4 a = src[2 * t];
    float4 b = full ? src[2 * t + 1] : make_float4(0.f, 0.f, 0.f, 0.f);

    float m = fmaxf(fmaxf(fmaxf(fabsf(a.x), fabsf(a.y)), fmaxf(fabsf(a.z), fabsf(a.w))),
                    fmaxf(fmaxf(fabsf(b.x), fabsf(b.y)), fmaxf(fabsf(b.z), fabsf(b.w))));

    // maxabs = mant * 2^E, mant in [0.5,1) => E = raw_exp - 126.
    // step = 2^(E-7) = 2^(raw-133)  -> float bits (raw-6)<<23
    // inv  = 2^(133-raw)            -> float bits (260-raw)<<23
    const unsigned raw = __float_as_uint(m) >> 23;          // m >= 0, no sign bit
    float step, inv;
    if (raw >= 7u && raw <= 254u) {                         // normal, non-degenerate path
        step = __uint_as_float((raw -   6u) << 23);
        inv  = __uint_as_float((260u - raw) << 23);
    } else if (m == 0.0f) {                                 // all-zero block -> output zeros
        step = 0.0f; inv = 0.0f;
    } else {                                                // subnormal maxabs (pathological)
        int e; (void)frexpf(m, &e);
        step = ldexpf(1.0f, e - 7);
        inv  = ldexpf(1.0f, 7 - e);
    }

    // rintf == round-half-to-even == jnp.round; clip AFTER rounding.
    #define QD(v) (fminf(fmaxf(rintf((v) * inv), -128.0f), 127.0f) * step)

    dst[2 * t] = make_float4(QD(a.x), QD(a.y), QD(a.z), QD(a.w));
    if (full) {
        dst[2 * t + 1] = make_float4(QD(b.x), QD(b.y), QD(b.z), QD(b.w));
    }
    #undef QD
}

extern "C" void kernel_launch(void* const* d_in, const int* in_sizes, int n_in,
                              void* d_out, int out_size)
{
    const float* x = (const float*)d_in[0];
    float* out = (float*)d_out;
    dim3 grid(NBLK / 256, ROWS, 1);   // (6, 8192) -> 49152 CTAs
    bfp_qdq_kernel<<<grid, 256>>>(x, out);
}